// round 14
// baseline (speedup 1.0000x reference)
#include <cuda_runtime.h>

// FWHT-128 over the last dim of three (4,32,4096,128) fp32 tensors.
// Converged optimum (R13): 256-bit non-coherent streaming loads
// (ld.global.nc.cs.v8.f32) + 256-bit streaming stores, 8 lanes per row
// (j = lane&7), 4 rows per warp, regs=32, occ ~76%, DRAM 87.3% (6917 GB/s)
// — at the mixed R/W HBM turnaround ceiling.
// This round: c0/c1 shuffle chains interleaved for dual-chain ILP.
//   In-register stages: h=1,2,4 (inside each 8-float chunk), h=64 (between chunks).
//   Shuffle stages:     h=8,16,32 -> __shfl_xor masks 1,2,4 (within 8-lane group).

__device__ __forceinline__ void ldg256_nc_cs(const float* p, float* r) {
    asm("ld.global.nc.cs.v8.f32 {%0,%1,%2,%3,%4,%5,%6,%7}, [%8];"
        : "=f"(r[0]), "=f"(r[1]), "=f"(r[2]), "=f"(r[3]),
          "=f"(r[4]), "=f"(r[5]), "=f"(r[6]), "=f"(r[7])
        : "l"(p));
}

__device__ __forceinline__ void stg256_cs(float* p, const float* r) {
    asm volatile("st.global.cs.v8.f32 [%0], {%1,%2,%3,%4,%5,%6,%7,%8};"
        :: "l"(p),
           "f"(r[0]), "f"(r[1]), "f"(r[2]), "f"(r[3]),
           "f"(r[4]), "f"(r[5]), "f"(r[6]), "f"(r[7])
        : "memory");
}

__global__ __launch_bounds__(256, 8) void fwht128_kernel(
    const float* __restrict__ q,
    const float* __restrict__ k,
    const float* __restrict__ v,
    float* __restrict__ out,
    int rowsPerArr)
{
    const int lane = threadIdx.x & 31;
    const int warpGlobal = (int)((blockIdx.x * blockDim.x + threadIdx.x) >> 5);
    const int row = warpGlobal * 4 + (lane >> 3);
    const int j = lane & 7;

    const float* __restrict__ src = (blockIdx.y == 0) ? q : (blockIdx.y == 1) ? k : v;

    const size_t base = (size_t)row * 128 + j * 8;   // float index, 32B-aligned

    float c0[8], c1[8];
    ldg256_nc_cs(src + base,      c0);   // elements 8j+0..7
    ldg256_nc_cs(src + base + 64, c1);   // elements 64+8j+0..7

    // ---- In-chunk stages h=1,2,4 ----
    #define CHUNK_H1(c) { float t; \
        t=c[0]; c[0]=t+c[1]; c[1]=t-c[1]; \
        t=c[2]; c[2]=t+c[3]; c[3]=t-c[3]; \
        t=c[4]; c[4]=t+c[5]; c[5]=t-c[5]; \
        t=c[6]; c[6]=t+c[7]; c[7]=t-c[7]; }
    #define CHUNK_H2(c) { float t; \
        t=c[0]; c[0]=t+c[2]; c[2]=t-c[2]; \
        t=c[1]; c[1]=t+c[3]; c[3]=t-c[3]; \
        t=c[4]; c[4]=t+c[6]; c[6]=t-c[6]; \
        t=c[5]; c[5]=t+c[7]; c[7]=t-c[7]; }
    #define CHUNK_H4(c) { float t; \
        t=c[0]; c[0]=t+c[4]; c[4]=t-c[4]; \
        t=c[1]; c[1]=t+c[5]; c[5]=t-c[5]; \
        t=c[2]; c[2]=t+c[6]; c[6]=t-c[6]; \
        t=c[3]; c[3]=t+c[7]; c[7]=t-c[7]; }
    CHUNK_H1(c0) CHUNK_H1(c1)
    CHUNK_H2(c0) CHUNK_H2(c1)
    CHUNK_H4(c0) CHUNK_H4(c1)

    // ---- Stages h=8,16,32: element bits 3,4,5 live in j -> masks 1,2,4 ----
    // Interleaved c0/c1 for two independent dependency chains.
    #pragma unroll
    for (int m = 1; m <= 4; m <<= 1) {
        const float sgn = (j & m) ? -1.0f : 1.0f;
        #pragma unroll
        for (int i = 0; i < 8; i++) {
            float p0 = __shfl_xor_sync(0xffffffffu, c0[i], m);
            float p1 = __shfl_xor_sync(0xffffffffu, c1[i], m);
            c0[i] = fmaf(c0[i], sgn, p0);
            c1[i] = fmaf(c1[i], sgn, p1);
        }
    }

    // ---- Stage h=64: between the two chunks; fold in final 1/sqrt(128) scale ----
    const float s = 0.08838834764831845f;
    #pragma unroll
    for (int i = 0; i < 8; i++) {
        float t = c0[i];
        c0[i] = (t + c1[i]) * s;
        c1[i] = (t - c1[i]) * s;
    }

    float* __restrict__ dst = out + (size_t)blockIdx.y * rowsPerArr * 128;
    stg256_cs(dst + base,      c0);
    stg256_cs(dst + base + 64, c1);
}

extern "C" void kernel_launch(void* const* d_in, const int* in_sizes, int n_in,
                              void* d_out, int out_size)
{
    const float* q = (const float*)d_in[0];
    const float* k = (const float*)d_in[1];
    const float* v = (const float*)d_in[2];
    float* out = (float*)d_out;

    const int rowsPerArr = in_sizes[0] / 128;   // 524288 (multiple of 32)
    const int rowsPerBlock = (256 / 32) * 4;    // 8 warps * 4 rows = 32
    const int blocksX = rowsPerArr / rowsPerBlock;

    dim3 grid(blocksX, 3, 1);
    fwht128_kernel<<<grid, 256>>>(q, k, v, out, rowsPerArr);
}

// round 16
// speedup vs baseline: 1.0058x; 1.0058x over previous
#include <cuda_runtime.h>

// FWHT-128 over the last dim of three (4,32,4096,128) fp32 tensors.
// Converged roofline kernel (R13 config, best measured: 224.83us,
// DRAM 87.3%, 6917 GB/s — the mixed R/W HBM turnaround ceiling).
// 256-bit non-coherent streaming loads (ld.global.nc.cs.v8.f32) +
// 256-bit streaming stores; 8 lanes per row (j = lane&7), 4 rows per warp.
// Each thread owns elements {8j..8j+7} and {64+8j..64+8j+7} of its row.
//   In-register stages: h=1,2,4 (inside each chunk), h=64 (between chunks).
//   Shuffle stages:     h=8,16,32 -> __shfl_xor masks 1,2,4 (within 8-lane group).

__device__ __forceinline__ void ldg256_nc_cs(const float* p, float* r) {
    asm("ld.global.nc.cs.v8.f32 {%0,%1,%2,%3,%4,%5,%6,%7}, [%8];"
        : "=f"(r[0]), "=f"(r[1]), "=f"(r[2]), "=f"(r[3]),
          "=f"(r[4]), "=f"(r[5]), "=f"(r[6]), "=f"(r[7])
        : "l"(p));
}

__device__ __forceinline__ void stg256_cs(float* p, const float* r) {
    asm volatile("st.global.cs.v8.f32 [%0], {%1,%2,%3,%4,%5,%6,%7,%8};"
        :: "l"(p),
           "f"(r[0]), "f"(r[1]), "f"(r[2]), "f"(r[3]),
           "f"(r[4]), "f"(r[5]), "f"(r[6]), "f"(r[7])
        : "memory");
}

__global__ __launch_bounds__(256, 8) void fwht128_kernel(
    const float* __restrict__ q,
    const float* __restrict__ k,
    const float* __restrict__ v,
    float* __restrict__ out,
    int rowsPerArr)
{
    const int lane = threadIdx.x & 31;
    const int j = lane & 7;
    // 8 warps/block * 4 rows/warp = 32 rows per block
    const int row = blockIdx.x * 32 + ((threadIdx.x >> 5) << 2) + (lane >> 3);

    const float* __restrict__ src = (blockIdx.y == 0) ? q : (blockIdx.y == 1) ? k : v;

    const size_t base = (size_t)row * 128 + j * 8;   // float index, 32B-aligned

    float c0[8], c1[8];
    ldg256_nc_cs(src + base,      c0);   // elements 8j+0..7
    ldg256_nc_cs(src + base + 64, c1);   // elements 64+8j+0..7

    // ---- In-chunk stages h=1,2,4 ----
    #define CHUNK_H1(c) { float t; \
        t=c[0]; c[0]=t+c[1]; c[1]=t-c[1]; \
        t=c[2]; c[2]=t+c[3]; c[3]=t-c[3]; \
        t=c[4]; c[4]=t+c[5]; c[5]=t-c[5]; \
        t=c[6]; c[6]=t+c[7]; c[7]=t-c[7]; }
    #define CHUNK_H2(c) { float t; \
        t=c[0]; c[0]=t+c[2]; c[2]=t-c[2]; \
        t=c[1]; c[1]=t+c[3]; c[3]=t-c[3]; \
        t=c[4]; c[4]=t+c[6]; c[6]=t-c[6]; \
        t=c[5]; c[5]=t+c[7]; c[7]=t-c[7]; }
    #define CHUNK_H4(c) { float t; \
        t=c[0]; c[0]=t+c[4]; c[4]=t-c[4]; \
        t=c[1]; c[1]=t+c[5]; c[5]=t-c[5]; \
        t=c[2]; c[2]=t+c[6]; c[6]=t-c[6]; \
        t=c[3]; c[3]=t+c[7]; c[7]=t-c[7]; }
    CHUNK_H1(c0) CHUNK_H1(c1)
    CHUNK_H2(c0) CHUNK_H2(c1)
    CHUNK_H4(c0) CHUNK_H4(c1)

    // ---- Stages h=8,16,32: element bits 3,4,5 live in j -> masks 1,2,4 ----
    // val_new = p + sgn*val  (sgn=+1 low side, -1 high side)
    #pragma unroll
    for (int m = 1; m <= 4; m <<= 1) {
        const float sgn = (j & m) ? -1.0f : 1.0f;
        #pragma unroll
        for (int i = 0; i < 8; i++) {
            float p = __shfl_xor_sync(0xffffffffu, c0[i], m);
            c0[i] = fmaf(c0[i], sgn, p);
        }
        #pragma unroll
        for (int i = 0; i < 8; i++) {
            float p = __shfl_xor_sync(0xffffffffu, c1[i], m);
            c1[i] = fmaf(c1[i], sgn, p);
        }
    }

    // ---- Stage h=64: between the two chunks; fold in final 1/sqrt(128) scale ----
    const float s = 0.08838834764831845f;
    #pragma unroll
    for (int i = 0; i < 8; i++) {
        float t = c0[i];
        c0[i] = (t + c1[i]) * s;
        c1[i] = (t - c1[i]) * s;
    }

    float* __restrict__ dst = out + (size_t)blockIdx.y * rowsPerArr * 128;
    stg256_cs(dst + base,      c0);
    stg256_cs(dst + base + 64, c1);
}

extern "C" void kernel_launch(void* const* d_in, const int* in_sizes, int n_in,
                              void* d_out, int out_size)
{
    const float* q = (const float*)d_in[0];
    const float* k = (const float*)d_in[1];
    const float* v = (const float*)d_in[2];
    float* out = (float*)d_out;

    const int rowsPerArr = in_sizes[0] / 128;   // 524288 (multiple of 32)
    const int blocksX = rowsPerArr / 32;        // 32 rows per block

    dim3 grid(blocksX, 3, 1);
    fwht128_kernel<<<grid, 256>>>(q, k, v, out, rowsPerArr);
}

// round 17
// speedup vs baseline: 1.0072x; 1.0014x over previous
#include <cuda_runtime.h>

// FWHT-128 over the last dim of three (4,32,4096,128) fp32 tensors.
// Variant of the converged config (R13/R16: 225.0us, DRAM 87.3%):
// loads stay ld.global.nc.cs.v8.f32 (read-once, evict-first), but stores
// switch from .cs (streaming straight to DRAM) to default writeback (.wb).
// Hypothesis: L2 (126MB, only 40% busy) batches dirty lines into larger
// writeback bursts -> fewer DRAM R/W bus turnarounds -> higher effective BW.
//   In-register stages: h=1,2,4 (inside each 8-float chunk), h=64 (between chunks).
//   Shuffle stages:     h=8,16,32 -> __shfl_xor masks 1,2,4 (within 8-lane group).

__device__ __forceinline__ void ldg256_nc_cs(const float* p, float* r) {
    asm("ld.global.nc.cs.v8.f32 {%0,%1,%2,%3,%4,%5,%6,%7}, [%8];"
        : "=f"(r[0]), "=f"(r[1]), "=f"(r[2]), "=f"(r[3]),
          "=f"(r[4]), "=f"(r[5]), "=f"(r[6]), "=f"(r[7])
        : "l"(p));
}

__device__ __forceinline__ void stg256_wb(float* p, const float* r) {
    asm volatile("st.global.v8.f32 [%0], {%1,%2,%3,%4,%5,%6,%7,%8};"
        :: "l"(p),
           "f"(r[0]), "f"(r[1]), "f"(r[2]), "f"(r[3]),
           "f"(r[4]), "f"(r[5]), "f"(r[6]), "f"(r[7])
        : "memory");
}

__global__ __launch_bounds__(256, 8) void fwht128_kernel(
    const float* __restrict__ q,
    const float* __restrict__ k,
    const float* __restrict__ v,
    float* __restrict__ out,
    int rowsPerArr)
{
    const int lane = threadIdx.x & 31;
    const int j = lane & 7;
    // 8 warps/block * 4 rows/warp = 32 rows per block
    const int row = blockIdx.x * 32 + ((threadIdx.x >> 5) << 2) + (lane >> 3);

    const float* __restrict__ src = (blockIdx.y == 0) ? q : (blockIdx.y == 1) ? k : v;

    const size_t base = (size_t)row * 128 + j * 8;   // float index, 32B-aligned

    float c0[8], c1[8];
    ldg256_nc_cs(src + base,      c0);   // elements 8j+0..7
    ldg256_nc_cs(src + base + 64, c1);   // elements 64+8j+0..7

    // ---- In-chunk stages h=1,2,4 ----
    #define CHUNK_H1(c) { float t; \
        t=c[0]; c[0]=t+c[1]; c[1]=t-c[1]; \
        t=c[2]; c[2]=t+c[3]; c[3]=t-c[3]; \
        t=c[4]; c[4]=t+c[5]; c[5]=t-c[5]; \
        t=c[6]; c[6]=t+c[7]; c[7]=t-c[7]; }
    #define CHUNK_H2(c) { float t; \
        t=c[0]; c[0]=t+c[2]; c[2]=t-c[2]; \
        t=c[1]; c[1]=t+c[3]; c[3]=t-c[3]; \
        t=c[4]; c[4]=t+c[6]; c[6]=t-c[6]; \
        t=c[5]; c[5]=t+c[7]; c[7]=t-c[7]; }
    #define CHUNK_H4(c) { float t; \
        t=c[0]; c[0]=t+c[4]; c[4]=t-c[4]; \
        t=c[1]; c[1]=t+c[5]; c[5]=t-c[5]; \
        t=c[2]; c[2]=t+c[6]; c[6]=t-c[6]; \
        t=c[3]; c[3]=t+c[7]; c[7]=t-c[7]; }
    CHUNK_H1(c0) CHUNK_H1(c1)
    CHUNK_H2(c0) CHUNK_H2(c1)
    CHUNK_H4(c0) CHUNK_H4(c1)

    // ---- Stages h=8,16,32: element bits 3,4,5 live in j -> masks 1,2,4 ----
    // val_new = p + sgn*val  (sgn=+1 low side, -1 high side)
    #pragma unroll
    for (int m = 1; m <= 4; m <<= 1) {
        const float sgn = (j & m) ? -1.0f : 1.0f;
        #pragma unroll
        for (int i = 0; i < 8; i++) {
            float p = __shfl_xor_sync(0xffffffffu, c0[i], m);
            c0[i] = fmaf(c0[i], sgn, p);
        }
        #pragma unroll
        for (int i = 0; i < 8; i++) {
            float p = __shfl_xor_sync(0xffffffffu, c1[i], m);
            c1[i] = fmaf(c1[i], sgn, p);
        }
    }

    // ---- Stage h=64: between the two chunks; fold in final 1/sqrt(128) scale ----
    const float s = 0.08838834764831845f;
    #pragma unroll
    for (int i = 0; i < 8; i++) {
        float t = c0[i];
        c0[i] = (t + c1[i]) * s;
        c1[i] = (t - c1[i]) * s;
    }

    float* __restrict__ dst = out + (size_t)blockIdx.y * rowsPerArr * 128;
    stg256_wb(dst + base,      c0);
    stg256_wb(dst + base + 64, c1);
}

extern "C" void kernel_launch(void* const* d_in, const int* in_sizes, int n_in,
                              void* d_out, int out_size)
{
    const float* q = (const float*)d_in[0];
    const float* k = (const float*)d_in[1];
    const float* v = (const float*)d_in[2];
    float* out = (float*)d_out;

    const int rowsPerArr = in_sizes[0] / 128;   // 524288 (multiple of 32)
    const int blocksX = rowsPerArr / 32;        // 32 rows per block

    dim3 grid(blocksX, 3, 1);
    fwht128_kernel<<<grid, 256>>>(q, k, v, out, rowsPerArr);
}